// round 14
// baseline (speedup 1.0000x reference)
#include <cuda_runtime.h>
#include <math.h>

#define NUM_NODES 17185
#define D 6
#define FEATS (NUM_NODES * D)   // 103110
#define BATCH 256
#define NPB 32                  // node lanes per block (= warp width)
#define WARPS 8                 // 256 threads
#define BSPLIT 4                // batch quarters across blocks
#define ITERS 8                 // batch rows per warp (64 rows / 8 warps)
#define NBLK ((NUM_NODES + NPB - 1) / NPB)  // 538
#define GRID (NBLK * BSPLIT)    // 2152
#define EPS 1e-5f

// Partials [blk][b]; tail reads coalesced across b. Every slot written each
// launch. __device__ global => no allocation.
__device__ float g_partial[NBLK * BATCH];
__device__ unsigned int g_ctr = 0;   // self-resetting arrival counter

__global__ __launch_bounds__(256, 3)
void fused_kernel(const float* __restrict__ data,
                  const float* __restrict__ w_blocks,
                  const float* __restrict__ b_blocks,
                  const float* __restrict__ bn_gamma,
                  const float* __restrict__ bn_beta,
                  const float* __restrict__ bn_mean,
                  const float* __restrict__ bn_var,
                  const float* __restrict__ fc_w,
                  const float* __restrict__ fc_b,
                  const float* __restrict__ bnf_gamma,
                  const float* __restrict__ bnf_beta,
                  const float* __restrict__ bnf_mean,
                  const float* __restrict__ bnf_var,
                  float* __restrict__ out)
{
    __shared__ unsigned int s_last;

    const int tid    = threadIdx.x;
    const int lane   = tid & 31;
    const int warp   = tid >> 5;              // 0..7
    const int blk    = blockIdx.x >> 2;       // node block 0..537
    const int bsplit = blockIdx.x & 3;        // batch quarter (siblings adjacent
    const int node   = blk * NPB + lane;      //  -> weight reuse in L2)
    const bool valid = (node < NUM_NODES);

    // ---- per-thread node state (registers), loaded once, reused 8x ----
    float W[36], bias[D], A[D];
    float CN = 0.0f;
    {
        const size_t wofs = (size_t)(valid ? node : 0) * 36;
        const float4* wp = reinterpret_cast<const float4*>(w_blocks + wofs);
        #pragma unroll
        for (int i = 0; i < 9; ++i) {
            float4 v = __ldg(&wp[i]);
            W[i*4+0] = v.x; W[i*4+1] = v.y; W[i*4+2] = v.z; W[i*4+3] = v.w;
        }
        const int f0 = (valid ? node : 0) * D;
        #pragma unroll
        for (int o = 0; o < D; ++o) {
            const int f = f0 + o;
            bias[o] = __ldg(&b_blocks[f]);
            const float rs = rsqrtf(__ldg(&bn_var[f]) + EPS);
            const float g  = __ldg(&bn_gamma[f]) * rs;
            const float fw = __ldg(&fc_w[f]);
            A[o]  = g * fw;
            CN   += (__ldg(&bn_beta[f]) - __ldg(&bn_mean[f]) * g) * fw;
        }
    }

    // ---- hot loop: depth-1 register prefetch, fully unrolled ----
    // warp handles b = bsplit*64 + bi*8 + warp, bi = 0..7 (step 8 rows).
    const float* p = data + (size_t)(bsplit * 64 + warp) * FEATS + (size_t)node * D;
    const size_t step = (size_t)WARPS * FEATS;

    float2 n0 = make_float2(0.f, 0.f), n1 = n0, n2 = n0;
    if (valid) {
        const float2* xp = reinterpret_cast<const float2*>(p);
        n0 = __ldcs(&xp[0]); n1 = __ldcs(&xp[1]); n2 = __ldcs(&xp[2]);
    }

    float keep = 0.0f;
    #pragma unroll
    for (int bi = 0; bi < ITERS; ++bi) {
        const float2 c0 = n0, c1 = n1, c2 = n2;
        if (bi + 1 < ITERS && valid) {        // prefetch next row NOW:
            const float2* q = reinterpret_cast<const float2*>(p + (size_t)(bi + 1) * step);
            n0 = __ldcs(&q[0]); n1 = __ldcs(&q[1]); n2 = __ldcs(&q[2]);
        }
        const float x[D] = {c0.x, c0.y, c1.x, c1.y, c2.x, c2.y};
        float acc = CN;
        #pragma unroll
        for (int o = 0; o < D; ++o) {
            float s = bias[o];
            #pragma unroll
            for (int i = 0; i < D; ++i)
                s = fmaf(x[i], W[o * D + i], s);
            s = fmaxf(s, 0.0f);               // ReLU
            acc = fmaf(s, A[o], acc);         // folded BN * fc_w
        }
        acc = valid ? acc : 0.0f;
        // Butterfly across node lanes (fixed order -> deterministic).
        #pragma unroll
        for (int off = 16; off > 0; off >>= 1)
            acc += __shfl_xor_sync(0xffffffffu, acc, off);
        if (lane == bi) keep = acc;           // lane bi owns row bi
    }
    if (lane < ITERS)
        g_partial[blk * BATCH + (bsplit * 64 + lane * 8 + warp)] = keep;

    // ---- last-block tail (CG-style fence protocol, tid0-only membar) ----
    __syncthreads();                          // stores ordered at CTA scope
    if (tid == 0) {
        __threadfence();                      // release to gpu scope
        const unsigned int old = atomicAdd(&g_ctr, 1u);
        s_last = (old == (unsigned)(GRID - 1)) ? 1u : 0u;
        if (s_last) atomicExch(&g_ctr, 0u);   // reset for next launch
    }
    __syncthreads();
    if (!s_last) return;
    if (tid == 0) __threadfence();            // acquire
    __syncthreads();

    {
        const int b = tid;                    // 256 threads = 256 batch rows
        float s0 = 0.f, s1 = 0.f, s2 = 0.f, s3 = 0.f;
        int k = 0;
        for (; k + 4 <= NBLK; k += 4) {       // fixed grouping -> deterministic
            s0 += g_partial[(k + 0) * BATCH + b];
            s1 += g_partial[(k + 1) * BATCH + b];
            s2 += g_partial[(k + 2) * BATCH + b];
            s3 += g_partial[(k + 3) * BATCH + b];
        }
        for (; k < NBLK; ++k) s0 += g_partial[k * BATCH + b];
        const float t  = ((s0 + s1) + (s2 + s3)) + fc_b[0];
        const float rs = rsqrtf(bnf_var[0] + EPS);
        const float y  = (t - bnf_mean[0]) * rs * bnf_gamma[0] + bnf_beta[0];
        out[b] = 1.0f / (1.0f + expf(-y));
    }
}

extern "C" void kernel_launch(void* const* d_in, const int* in_sizes, int n_in,
                              void* d_out, int out_size) {
    const float* data      = (const float*)d_in[0];
    const float* w_blocks  = (const float*)d_in[1];
    const float* b_blocks  = (const float*)d_in[2];
    const float* bn_gamma  = (const float*)d_in[3];
    const float* bn_beta   = (const float*)d_in[4];
    const float* bn_mean   = (const float*)d_in[5];
    const float* bn_var    = (const float*)d_in[6];
    const float* fc_w      = (const float*)d_in[7];
    const float* fc_b      = (const float*)d_in[8];
    const float* bnf_gamma = (const float*)d_in[9];
    const float* bnf_beta  = (const float*)d_in[10];
    const float* bnf_mean  = (const float*)d_in[11];
    const float* bnf_var   = (const float*)d_in[12];
    float* out = (float*)d_out;

    fused_kernel<<<GRID, 256>>>(data, w_blocks, b_blocks, bn_gamma, bn_beta,
                                bn_mean, bn_var, fc_w, fc_b, bnf_gamma,
                                bnf_beta, bnf_mean, bnf_var, out);
}

// round 15
// speedup vs baseline: 1.1063x; 1.1063x over previous
#include <cuda_runtime.h>
#include <math.h>
#include <stdint.h>

#define NUM_NODES 17185
#define D 6
#define FEATS (NUM_NODES * D)            // 103110
#define BATCH 256
#define NPB 64                            // nodes per block
#define NBLK ((NUM_NODES + NPB - 1) / NPB)  // 269
#define EPS 1e-5f

#define DEPTH 3                           // mbarrier ring depth
#define RPS 8                             // rows per stage (one per warp-pair)
#define NSTAGE (BATCH / RPS)              // 32
#define ROW_BYTES 1552                    // 64*24 + 16 slack (16B multiple)
#define ROW_PITCH 1568                    // smem row pitch, 16B aligned
#define STAGE_BYTES (RPS * ROW_PITCH)     // 12544
#define TOTAL_BYTES ((size_t)BATCH * FEATS * 4)

// Partials [blk][b]; tail reads coalesced across b. Every slot written each
// launch. __device__ global => no allocation.
__device__ float g_partial[NBLK * BATCH];
__device__ unsigned int g_ctr = 0;        // self-resetting arrival counter

__device__ __forceinline__ uint32_t smem_u32(const void* p) {
    uint32_t a;
    asm("{ .reg .u64 t; cvta.to.shared.u64 t, %1; cvt.u32.u64 %0, t; }"
        : "=r"(a) : "l"(p));
    return a;
}
__device__ __forceinline__ void mbar_init(uint32_t mb, uint32_t cnt) {
    asm volatile("mbarrier.init.shared.b64 [%0], %1;" :: "r"(mb), "r"(cnt) : "memory");
}
__device__ __forceinline__ void mbar_expect_tx(uint32_t mb, uint32_t tx) {
    asm volatile("mbarrier.arrive.expect_tx.shared.b64 _, [%0], %1;"
                 :: "r"(mb), "r"(tx) : "memory");
}
__device__ __forceinline__ void mbar_wait(uint32_t mb, uint32_t parity) {
    asm volatile(
        "{\n\t.reg .pred P;\n\t"
        "W%=:\n\t"
        "mbarrier.try_wait.parity.shared::cta.b64 P, [%0], %1, 0x989680;\n\t"
        "@P bra D%=;\n\t"
        "bra W%=;\n\t"
        "D%=:\n\t}"
        :: "r"(mb), "r"(parity) : "memory");
}
__device__ __forceinline__ void bulk_g2s(uint32_t dst, const void* src,
                                         uint32_t bytes, uint32_t mb) {
    asm volatile(
        "cp.async.bulk.shared::cta.global.mbarrier::complete_tx::bytes "
        "[%0], [%1], %2, [%3];"
        :: "r"(dst), "l"(src), "r"(bytes), "r"(mb) : "memory");
}

__global__ __launch_bounds__(512, 1)
void fused_kernel(const float* __restrict__ data,
                  const float* __restrict__ w_blocks,
                  const float* __restrict__ b_blocks,
                  const float* __restrict__ bn_gamma,
                  const float* __restrict__ bn_beta,
                  const float* __restrict__ bn_mean,
                  const float* __restrict__ bn_var,
                  const float* __restrict__ fc_w,
                  const float* __restrict__ fc_b,
                  const float* __restrict__ bnf_gamma,
                  const float* __restrict__ bnf_beta,
                  const float* __restrict__ bnf_mean,
                  const float* __restrict__ bnf_var,
                  float* __restrict__ out)
{
    __shared__ __align__(128) char sData[DEPTH * STAGE_BYTES];   // 37.6 KB ring
    __shared__ __align__(16) unsigned long long sMbarStore[DEPTH];
    __shared__ float sW[NPB * 37];                               // 9.25 KB
    __shared__ float sPair[RPS][32];
    __shared__ unsigned int s_last;

    const int tid     = threadIdx.x;
    const int lane    = tid & 31;
    const int warp    = tid >> 5;       // 0..15
    const int pair    = warp >> 1;      // 0..7  (row within stage)
    const int side    = warp & 1;       // which half of the 64 nodes
    const int node_ln = tid & 63;       // = side*32 + lane
    const int node0   = blockIdx.x * NPB;
    const int node    = node0 + node_ln;
    const bool valid  = (node < NUM_NODES);

    const uint32_t sdata_u = smem_u32(sData);
    uint32_t mb[DEPTH];
    #pragma unroll
    for (int q = 0; q < DEPTH; ++q) mb[q] = smem_u32(&sMbarStore[q]);

    if (tid == 0) {
        #pragma unroll
        for (int q = 0; q < DEPTH; ++q) mbar_init(mb[q], 1);
    }
    __syncthreads();

    // ---- TMA stage issue (tid0 only): 8 bulk copies + expect_tx ----
    auto issue_stage = [&](int s, int slot) {
        uint32_t szs[RPS];
        uint32_t tx = 0;
        #pragma unroll
        for (int r = 0; r < RPS; ++r) {
            const size_t off = (((size_t)(s * RPS + r)) * FEATS + (size_t)node0 * D) * 4;
            const size_t a   = off & ~(size_t)15;       // align down (phase 0/8)
            uint32_t sz = ROW_BYTES;
            const size_t rem = TOTAL_BYTES - a;
            if (rem < sz) sz = (uint32_t)rem & ~15u;    // clamp at buffer tail
            szs[r] = sz;
            tx += sz;
        }
        mbar_expect_tx(mb[slot], tx);
        #pragma unroll
        for (int r = 0; r < RPS; ++r) {
            const size_t off = (((size_t)(s * RPS + r)) * FEATS + (size_t)node0 * D) * 4;
            const size_t a   = off & ~(size_t)15;
            bulk_g2s(sdata_u + slot * STAGE_BYTES + r * ROW_PITCH,
                     (const char*)data + a, szs[r], mb[slot]);
        }
    };

    // Prologue: get DEPTH stages in flight, then overlap weight staging.
    if (tid == 0) {
        issue_stage(0, 0);
        issue_stage(1, 1);
        issue_stage(2, 2);
    }

    // Coalesced weight staging into padded smem (once per block).
    {
        const float* wsrc = w_blocks + (size_t)node0 * 36;
        const int wlim = NUM_NODES * 36 - node0 * 36;
        for (int i = tid; i < NPB * 36; i += 512)
            sW[(i / 36) * 37 + (i % 36)] = (i < wlim) ? wsrc[i] : 0.0f;
    }
    __syncthreads();

    float W[36], bias[D], A[D];
    float CN = 0.0f;
    {
        const float* wrow = &sW[node_ln * 37];
        #pragma unroll
        for (int k = 0; k < 36; ++k) W[k] = wrow[k];
        const int f0 = (valid ? node : 0) * D;
        #pragma unroll
        for (int o = 0; o < D; ++o) {
            const int f = f0 + o;
            bias[o] = __ldg(&b_blocks[f]);
            const float rs = rsqrtf(__ldg(&bn_var[f]) + EPS);
            const float g  = __ldg(&bn_gamma[f]) * rs;
            const float fw = __ldg(&fc_w[f]);
            A[o]  = valid ? (g * fw) : 0.0f;
            CN   += valid ? ((__ldg(&bn_beta[f]) - __ldg(&bn_mean[f]) * g) * fw) : 0.0f;
        }
        if (!valid) {
            #pragma unroll
            for (int k = 0; k < 36; ++k) W[k] = 0.0f;
            #pragma unroll
            for (int o = 0; o < D; ++o) bias[o] = 0.0f;
        }
    }

    // ---- mainloop: TMA-fed stages; warp-pair `pair` computes row b=s*8+pair ----
    float keep = 0.0f;
    int slot = 0, par = 0;
    #pragma unroll 1
    for (int s = 0; s < NSTAGE; ++s) {
        mbar_wait(mb[slot], par);

        const int b  = s * RPS + pair;
        const int ph = (b & 1) ? 2 : 0;                 // 8B phase in floats
        const float* rp = reinterpret_cast<const float*>(
            sData + slot * STAGE_BYTES + pair * ROW_PITCH) + ph + node_ln * D;

        const float2 x01 = *reinterpret_cast<const float2*>(rp + 0);
        const float2 x23 = *reinterpret_cast<const float2*>(rp + 2);
        const float2 x45 = *reinterpret_cast<const float2*>(rp + 4);
        const float x[D] = {x01.x, x01.y, x23.x, x23.y, x45.x, x45.y};

        float acc = CN;
        #pragma unroll
        for (int o = 0; o < D; ++o) {
            float t = bias[o];
            #pragma unroll
            for (int i = 0; i < D; ++i)
                t = fmaf(x[i], W[o * D + i], t);
            t = fmaxf(t, 0.0f);            // ReLU (also squashes NaN from OOB junk)
            acc = fmaf(t, A[o], acc);      // folded BN * fc_w
        }
        // Butterfly across this warp's 32 node lanes (fixed order, deterministic).
        #pragma unroll
        for (int off = 16; off > 0; off >>= 1)
            acc += __shfl_xor_sync(0xffffffffu, acc, off);
        if (lane == s) keep = acc;         // lane s owns b = s*8+pair

        __syncthreads();                   // slot fully consumed
        if (tid == 0 && s + DEPTH < NSTAGE) issue_stage(s + DEPTH, slot);
        if (++slot == DEPTH) { slot = 0; par ^= 1; }
    }

    // Combine the two 32-node halves per (pair, b): side0 stages, side1 adds.
    if (side == 0) sPair[pair][lane] = keep;
    __syncthreads();
    if (side == 1)
        g_partial[blockIdx.x * BATCH + (lane * RPS + pair)] = keep + sPair[pair][lane];

    // ---- last-block tail (deterministic fixed-order reduction) ----
    __syncthreads();
    if (tid == 0) {
        __threadfence();
        const unsigned int old = atomicAdd(&g_ctr, 1u);
        s_last = (old == (unsigned)(NBLK - 1)) ? 1u : 0u;
        if (s_last) atomicExch(&g_ctr, 0u);
    }
    __syncthreads();
    if (!s_last) return;
    if (tid == 0) __threadfence();
    __syncthreads();

    if (tid < BATCH) {
        const int b = tid;
        float s0 = 0.f, s1 = 0.f, s2 = 0.f, s3 = 0.f;
        int k = 0;
        for (; k + 4 <= NBLK; k += 4) {    // fixed grouping -> deterministic
            s0 += g_partial[(k + 0) * BATCH + b];
            s1 += g_partial[(k + 1) * BATCH + b];
            s2 += g_partial[(k + 2) * BATCH + b];
            s3 += g_partial[(k + 3) * BATCH + b];
        }
        for (; k < NBLK; ++k) s0 += g_partial[k * BATCH + b];
        const float t  = ((s0 + s1) + (s2 + s3)) + fc_b[0];
        const float rs = rsqrtf(bnf_var[0] + EPS);
        const float y  = (t - bnf_mean[0]) * rs * bnf_gamma[0] + bnf_beta[0];
        out[b] = 1.0f / (1.0f + expf(-y));
    }
}

extern "C" void kernel_launch(void* const* d_in, const int* in_sizes, int n_in,
                              void* d_out, int out_size) {
    const float* data      = (const float*)d_in[0];
    const float* w_blocks  = (const float*)d_in[1];
    const float* b_blocks  = (const float*)d_in[2];
    const float* bn_gamma  = (const float*)d_in[3];
    const float* bn_beta   = (const float*)d_in[4];
    const float* bn_mean   = (const float*)d_in[5];
    const float* bn_var    = (const float*)d_in[6];
    const float* fc_w      = (const float*)d_in[7];
    const float* fc_b      = (const float*)d_in[8];
    const float* bnf_gamma = (const float*)d_in[9];
    const float* bnf_beta  = (const float*)d_in[10];
    const float* bnf_mean  = (const float*)d_in[11];
    const float* bnf_var   = (const float*)d_in[12];
    float* out = (float*)d_out;

    fused_kernel<<<NBLK, 512>>>(data, w_blocks, b_blocks, bn_gamma, bn_beta,
                                bn_mean, bn_var, fc_w, fc_b, bnf_gamma,
                                bnf_beta, bnf_mean, bnf_var, out);
}

// round 16
// speedup vs baseline: 1.1525x; 1.0417x over previous
#include <cuda_runtime.h>
#include <math.h>

#define NUM_NODES 17185
#define D 6
#define FEATS (NUM_NODES * D)               // 103110
#define BATCH 256
#define NPB 16                              // nodes per block (16 x 2 halves = 32 lanes)
#define WARPS 8                             // 256 threads
#define ITERS 32                            // batch rows per warp (256 / 8)
#define NBLK ((NUM_NODES + NPB - 1) / NPB)  // 1075
#define EPS 1e-5f

// Partials [blk][b]; tail reads coalesced across b. Every slot written each
// launch. __device__ global => no allocation.
__device__ float g_partial[NBLK * BATCH];
__device__ unsigned int g_ctr = 0;          // self-resetting arrival counter

__global__ __launch_bounds__(256, 4)
void fused_kernel(const float* __restrict__ data,
                  const float* __restrict__ w_blocks,
                  const float* __restrict__ b_blocks,
                  const float* __restrict__ bn_gamma,
                  const float* __restrict__ bn_beta,
                  const float* __restrict__ bn_mean,
                  const float* __restrict__ bn_var,
                  const float* __restrict__ fc_w,
                  const float* __restrict__ fc_b,
                  const float* __restrict__ bnf_gamma,
                  const float* __restrict__ bnf_beta,
                  const float* __restrict__ bnf_mean,
                  const float* __restrict__ bnf_var,
                  float* __restrict__ out)
{
    __shared__ float sW[NPB * 36];          // 2.25 KB coalesced weight stage
    __shared__ unsigned int s_last;

    const int tid   = threadIdx.x;
    const int lane  = tid & 31;
    const int warp  = tid >> 5;             // 0..7 -> batch rows b = i*8+warp
    const int nl    = lane >> 1;            // node within block (lane pair)
    const int h     = lane & 1;             // output half: o = h*3 .. h*3+2
    const int node0 = blockIdx.x * NPB;
    const int node  = node0 + nl;
    const bool valid = (node < NUM_NODES);
    const int nclamp = valid ? node : (NUM_NODES - 1);   // in-bounds load addr

    // ---- coalesced weight staging (576 contiguous floats) ----
    for (int i = tid; i < NPB * 36; i += 256) {
        const int gi = node0 * 36 + i;
        sW[i] = (gi < NUM_NODES * 36) ? w_blocks[gi] : 0.0f;
    }
    __syncthreads();

    // ---- per-thread HALF-node state: 18 W + 3 bias + 3 A + CN ----
    float W[18], bias[3], A[3];
    float CN = 0.0f;
    #pragma unroll
    for (int oo = 0; oo < 3; ++oo) {
        const int o = h * 3 + oo;
        #pragma unroll
        for (int k = 0; k < D; ++k)
            W[oo * D + k] = sW[nl * 36 + o * D + k];
        const int f = (valid ? node : 0) * D + o;
        bias[oo] = __ldg(&b_blocks[f]);
        const float rs = rsqrtf(__ldg(&bn_var[f]) + EPS);
        const float g  = __ldg(&bn_gamma[f]) * rs;
        const float fw = __ldg(&fc_w[f]);
        A[oo] = valid ? (g * fw) : 0.0f;    // invalid half contributes exactly 0
        CN   += valid ? ((__ldg(&bn_beta[f]) - __ldg(&bn_mean[f]) * g) * fw) : 0.0f;
    }

    // ---- hot loop: 32 rows, depth-1 prefetch, butterfly + lane capture ----
    // Lane pairs read the same 24 B (warp covers 16 nodes = 384 B contiguous).
    const float* pbase = data + (size_t)warp * FEATS + (size_t)nclamp * D;
    const size_t step  = (size_t)WARPS * FEATS;          // b += 8 per iter

    const float2* xp0 = reinterpret_cast<const float2*>(pbase);
    float2 n0 = xp0[0], n1 = xp0[1], n2 = xp0[2];

    float keep = 0.0f;
    #pragma unroll
    for (int i = 0; i < ITERS; ++i) {
        const float2 c0 = n0, c1 = n1, c2 = n2;
        if (i + 1 < ITERS) {                             // prefetch next row
            const float2* q = reinterpret_cast<const float2*>(pbase + (size_t)(i + 1) * step);
            n0 = q[0]; n1 = q[1]; n2 = q[2];
        }
        const float x[D] = {c0.x, c0.y, c1.x, c1.y, c2.x, c2.y};
        float acc = CN;
        #pragma unroll
        for (int oo = 0; oo < 3; ++oo) {                 // this thread's 3 outputs
            float s = bias[oo];
            #pragma unroll
            for (int k = 0; k < D; ++k)
                s = fmaf(x[k], W[oo * D + k], s);
            s = fmaxf(s, 0.0f);                          // ReLU
            acc = fmaf(s, A[oo], acc);                   // folded BN * fc_w
        }
        // Butterfly over 32 lanes = sum over 16 nodes x 2 halves (fixed
        // order -> deterministic). Lane i keeps row b = i*8 + warp.
        #pragma unroll
        for (int off = 16; off > 0; off >>= 1)
            acc += __shfl_xor_sync(0xffffffffu, acc, off);
        if (lane == i) keep = acc;
    }
    g_partial[blockIdx.x * BATCH + (lane * WARPS + warp)] = keep;

    // ---- last-block tail (deterministic fixed-order reduction) ----
    __syncthreads();
    if (tid == 0) {
        __threadfence();                                 // release
        const unsigned int old = atomicAdd(&g_ctr, 1u);
        s_last = (old == (unsigned)(NBLK - 1)) ? 1u : 0u;
        if (s_last) atomicExch(&g_ctr, 0u);              // reset for next launch
    }
    __syncthreads();
    if (!s_last) return;
    if (tid == 0) __threadfence();                       // acquire
    __syncthreads();

    {
        const int b = tid;                               // 256 threads = 256 rows
        float s0 = 0.f, s1 = 0.f, s2 = 0.f, s3 = 0.f;
        int k = 0;
        for (; k + 4 <= NBLK; k += 4) {                  // fixed grouping
            s0 += g_partial[(k + 0) * BATCH + b];        // coalesced across b
            s1 += g_partial[(k + 1) * BATCH + b];
            s2 += g_partial[(k + 2) * BATCH + b];
            s3 += g_partial[(k + 3) * BATCH + b];
        }
        for (; k < NBLK; ++k) s0 += g_partial[k * BATCH + b];
        const float t  = ((s0 + s1) + (s2 + s3)) + fc_b[0];
        const float rs = rsqrtf(bnf_var[0] + EPS);
        const float y  = (t - bnf_mean[0]) * rs * bnf_gamma[0] + bnf_beta[0];
        out[b] = 1.0f / (1.0f + expf(-y));
    }
}

extern "C" void kernel_launch(void* const* d_in, const int* in_sizes, int n_in,
                              void* d_out, int out_size) {
    const float* data      = (const float*)d_in[0];
    const float* w_blocks  = (const float*)d_in[1];
    const float* b_blocks  = (const float*)d_in[2];
    const float* bn_gamma  = (const float*)d_in[3];
    const float* bn_beta   = (const float*)d_in[4];
    const float* bn_mean   = (const float*)d_in[5];
    const float* bn_var    = (const float*)d_in[6];
    const float* fc_w      = (const float*)d_in[7];
    const float* fc_b      = (const float*)d_in[8];
    const float* bnf_gamma = (const float*)d_in[9];
    const float* bnf_beta  = (const float*)d_in[10];
    const float* bnf_mean  = (const float*)d_in[11];
    const float* bnf_var   = (const float*)d_in[12];
    float* out = (float*)d_out;

    fused_kernel<<<NBLK, 256>>>(data, w_blocks, b_blocks, bn_gamma, bn_beta,
                                bn_mean, bn_var, fc_w, fc_b, bnf_gamma,
                                bnf_beta, bnf_mean, bnf_var, out);
}